// round 15
// baseline (speedup 1.0000x reference)
#include <cuda_runtime.h>
#include <cuda_bf16.h>
#include <stdint.h>
#include <math.h>

#define NB 32
#define CC 256
#define HW 3136
#define PI_HALF 1.57079632679489662f

__device__ __nv_bfloat16 g_xh[NB][CC][HW];
__device__ __nv_bfloat16 g_xl[NB][CC][HW];
__device__ __nv_bfloat16 g_xgk[NB][98][2][256 * 40];   // packed x chunks (80B rows)
__device__ float g_gramp[3][NB][CC][CC];
__device__ float g_rowsum[NB][CC];
__device__ float g_u[NB][CC];
__device__ float g_v[NB][CC];
__device__ __nv_bfloat16 g_wpk[2][16][256 * 24];       // packed Wp3 (48B rows)
__device__ __nv_bfloat16 g_t7k[NB][2][16][256 * 24];   // packed t7^T (48B rows)

__device__ __forceinline__ uint32_t smem_u32(const void* p) {
    uint32_t a;
    asm("{ .reg .u64 t; cvta.to.shared.u64 t, %1; cvt.u32.u64 %0, t; }"
        : "=r"(a) : "l"(p));
    return a;
}
__device__ __forceinline__ void bulkcp(uint32_t dst, const void* src,
                                       uint32_t bytes, uint32_t mbar) {
    asm volatile(
        "cp.async.bulk.shared::cta.global.mbarrier::complete_tx::bytes "
        "[%0], [%1], %2, [%3];"
        :: "r"(dst), "l"(src), "r"(bytes), "r"(mbar) : "memory");
}
#define MBAR_INIT(a, c) asm volatile("mbarrier.init.shared.b64 [%0], %1;" :: "r"(a), "r"((uint32_t)(c)) : "memory")
#define MBAR_EXPECT(a, b) asm volatile("mbarrier.arrive.expect_tx.shared.b64 _, [%0], %1;" :: "r"(a), "r"((uint32_t)(b)) : "memory")
#define MBAR_WAIT(a, ph) do {                                                   \
    uint32_t _m = (a), _p = (uint32_t)(ph), _d;                                 \
    asm volatile("{\n\t.reg .pred p;\n\t"                                       \
        "mbarrier.try_wait.parity.acquire.cta.shared::cta.b64 p, [%1], %2;\n\t" \
        "selp.b32 %0, 1, 0, p;\n\t}" : "=r"(_d) : "r"(_m), "r"(_p) : "memory"); \
    if (!_d) { asm volatile("{\n\t.reg .pred P1;\n\tWL_%=:\n\t"                 \
        "mbarrier.try_wait.parity.acquire.cta.shared::cta.b64 P1, [%0], %1, 0x989680;\n\t" \
        "@P1 bra.uni WD_%=;\n\tbra.uni WL_%=;\n\tWD_%=:\n\t}"                   \
        :: "r"(_m), "r"(_p) : "memory"); }                                      \
} while (0)

__device__ __forceinline__ void ldsm4(uint32_t r[4], uint32_t a) {
    asm volatile("ldmatrix.sync.aligned.m8n8.x4.shared.b16 {%0,%1,%2,%3}, [%4];"
                 : "=r"(r[0]), "=r"(r[1]), "=r"(r[2]), "=r"(r[3]) : "r"(a));
}
__device__ __forceinline__ void ldsm4t(uint32_t r[4], uint32_t a) {
    asm volatile("ldmatrix.sync.aligned.m8n8.x4.trans.shared.b16 {%0,%1,%2,%3}, [%4];"
                 : "=r"(r[0]), "=r"(r[1]), "=r"(r[2]), "=r"(r[3]) : "r"(a));
}
__device__ __forceinline__ void mma_bf16(float c[4], const uint32_t a[4],
                                         const uint32_t b[2]) {
    asm volatile(
        "mma.sync.aligned.m16n8k16.row.col.f32.bf16.bf16.f32 "
        "{%0,%1,%2,%3}, {%4,%5,%6,%7}, {%8,%9}, {%0,%1,%2,%3};"
        : "+f"(c[0]), "+f"(c[1]), "+f"(c[2]), "+f"(c[3])
        : "r"(a[0]), "r"(a[1]), "r"(a[2]), "r"(a[3]), "r"(b[0]), "r"(b[1]));
}
__device__ __forceinline__ uint32_t pk2(__nv_bfloat16 a, __nv_bfloat16 b) {
    unsigned short ua = *(unsigned short*)&a, ub = *(unsigned short*)&b;
    return (uint32_t)ua | ((uint32_t)ub << 16);
}
__device__ __forceinline__ float bflo(uint32_t v) {
    unsigned short u = (unsigned short)(v & 0xffffu);
    return __bfloat162float(*(__nv_bfloat16*)&u);
}
__device__ __forceinline__ float bfhi(uint32_t v) {
    unsigned short u = (unsigned short)(v >> 16);
    return __bfloat162float(*(__nv_bfloat16*)&u);
}

// ---- prep: x -> bf16 hi/lo (linear + gram-packed) + rowsums ------------------
__global__ void k_prep(const float* __restrict__ x) {
    const int n = blockIdx.y, c = blockIdx.x, t = threadIdx.x;
    const float4* row = (const float4*)(x + ((size_t)n * CC + c) * HW);
    uint2* oh = (uint2*)&g_xh[n][c][0];
    uint2* ol = (uint2*)&g_xl[n][c][0];
    float s = 0.f;
    for (int u = t; u < HW / 4; u += 256) {
        float4 v = row[u];
        s += v.x + v.y + v.z + v.w;
        __nv_bfloat16 h0 = __float2bfloat16(v.x), h1 = __float2bfloat16(v.y);
        __nv_bfloat16 h2 = __float2bfloat16(v.z), h3 = __float2bfloat16(v.w);
        uint2 ph, pl;
        ph.x = pk2(h0, h1); ph.y = pk2(h2, h3);
        pl.x = pk2(__float2bfloat16(v.x - __bfloat162float(h0)),
                   __float2bfloat16(v.y - __bfloat162float(h1)));
        pl.y = pk2(__float2bfloat16(v.z - __bfloat162float(h2)),
                   __float2bfloat16(v.w - __bfloat162float(h3)));
        oh[u] = ph; ol[u] = pl;
        char* pk = (char*)&g_xgk[n][u >> 3][0][0] + c * 80 + (u & 7) * 8;
        *(uint2*)pk = ph;
        *(uint2*)(pk + 20480) = pl;
    }
#pragma unroll
    for (int o = 16; o; o >>= 1) s += __shfl_down_sync(0xffffffffu, s, o);
    __shared__ float red[8];
    if ((t & 31) == 0) red[t >> 5] = s;
    __syncthreads();
    if (t == 0) {
        float tt = 0.f;
#pragma unroll
        for (int q = 0; q < 8; q++) tt += red[q];
        g_rowsum[n][c] = tt;
    }
}

__global__ void k_wprep(const float* __restrict__ w) {
    const int o = blockIdx.x, i = threadIdx.x;
    const float v = w[o * 256 + i];
    __nv_bfloat16 h = __float2bfloat16(v);
    g_wpk[0][i >> 4][o * 24 + (i & 15)] = h;
    g_wpk[1][i >> 4][o * 24 + (i & 15)] =
        __float2bfloat16(v - __bfloat162float(h));
}

__global__ void k_uv(const float* __restrict__ Wg1, const float* __restrict__ Wg2) {
    const int n = blockIdx.x, t = threadIdx.x;
    __shared__ float ss[256];
    ss[t] = g_rowsum[n][t];
    __syncthreads();
    const int g = t >> 5, r = t & 31;
    float u = 0.f, v = 0.f;
#pragma unroll
    for (int i = 0; i < 32; i++) {
        u += Wg1[(g * 32 + r) * 32 + i] * ss[g * 32 + i];
        v += Wg2[(g * 32 + r) * 32 + i] * ss[g * 32 + i];
    }
    g_u[n][t] = u;
    g_v[n][t] = v;
}

// ---- Gram = x x^T, bulk-copy chunks, symmetric-tile, K-split x3 --------------
#define GSTRIDE 80u
#define GCH 10240
#define GRAM_SMEM (8 * GCH)

__global__ __launch_bounds__(256, 2) void k_gram() {
    extern __shared__ char sm[];
    __shared__ alignas(8) uint64_t s_mb[2];
    const int q = blockIdx.x, n = blockIdx.y, ks = blockIdx.z;
    const int c0 = (q == 1) ? 128 : 0;
    const int d0 = (q == 0) ? 0 : 128;
    const bool diag = (q < 2);
    const int tid = threadIdx.x, lane = tid & 31, wid = tid >> 5;
    const int m0w = (wid & 1) * 64, n0w = (wid >> 1) * 32;
    const uint32_t smb = smem_u32(sm);
    const uint32_t mb0 = smem_u32(&s_mb[0]), mb1 = mb0 + 8;

    const int a_r = lane & 15, a_kb = (lane >> 4) * 16;
    const int b_r = (lane & 7) + 8 * (lane >> 4);
    const int b_kb = ((lane >> 3) & 1) * 16;

    float acc[4][4][4];
#pragma unroll
    for (int i = 0; i < 4; i++)
#pragma unroll
        for (int j = 0; j < 4; j++)
#pragma unroll
            for (int p = 0; p < 4; p++) acc[i][j][p] = 0.f;

    const int ck0 = ks * 33;
    const int nck = (ks < 2) ? 33 : 32;

    auto issueG = [&](int ci, int buf) {   // tid 0 only
        const uint32_t mb = buf ? mb1 : mb0;
        const char* base = (const char*)&g_xgk[n][ck0 + ci][0][0];
        MBAR_EXPECT(mb, diag ? 2 * GCH : 4 * GCH);
        bulkcp(smb + (buf * 2 + 0) * GCH, base + c0 * 80, GCH, mb);
        bulkcp(smb + (buf * 2 + 1) * GCH, base + 20480 + c0 * 80, GCH, mb);
        if (!diag) {
            bulkcp(smb + 4 * GCH + (buf * 2 + 0) * GCH, base + d0 * 80, GCH, mb);
            bulkcp(smb + 4 * GCH + (buf * 2 + 1) * GCH, base + 20480 + d0 * 80, GCH, mb);
        }
    };

    if (tid == 0) { MBAR_INIT(mb0, 1); MBAR_INIT(mb1, 1); }
    __syncthreads();
    if (tid == 0) issueG(0, 0);
    int ph0 = 0, ph1 = 0;

    for (int ci = 0; ci < nck; ci++) {
        const int buf = ci & 1;
        __syncthreads();                          // prev chunk fully consumed
        if (ci < nck - 1 && tid == 0) issueG(ci + 1, buf ^ 1);
        if (buf == 0) { MBAR_WAIT(mb0, ph0); ph0 ^= 1; }
        else          { MBAR_WAIT(mb1, ph1); ph1 ^= 1; }

        const uint32_t aHb = smb + (buf * 2 + 0) * GCH;
        const uint32_t aLb = smb + (buf * 2 + 1) * GCH;
        const uint32_t bHb = diag ? aHb : smb + 4 * GCH + (buf * 2 + 0) * GCH;
        const uint32_t bLb = diag ? aLb : smb + 4 * GCH + (buf * 2 + 1) * GCH;
#pragma unroll
        for (int kk = 0; kk < 2; kk++) {
            const uint32_t kbo = kk * 32;
            uint32_t a[4][4], bh[4][2], bl[4][2];
#pragma unroll
            for (int mt = 0; mt < 4; mt++)
                ldsm4(a[mt], aHb + (uint32_t)(m0w + mt * 16 + a_r) * GSTRIDE + a_kb + kbo);
#pragma unroll
            for (int nt2 = 0; nt2 < 2; nt2++) {
                const uint32_t ro = (uint32_t)(n0w + nt2 * 16 + b_r) * GSTRIDE + b_kb + kbo;
                uint32_t t[4];
                ldsm4(t, bHb + ro);
                bh[nt2 * 2][0] = t[0]; bh[nt2 * 2][1] = t[1];
                bh[nt2 * 2 + 1][0] = t[2]; bh[nt2 * 2 + 1][1] = t[3];
                ldsm4(t, bLb + ro);
                bl[nt2 * 2][0] = t[0]; bl[nt2 * 2][1] = t[1];
                bl[nt2 * 2 + 1][0] = t[2]; bl[nt2 * 2 + 1][1] = t[3];
            }
#pragma unroll
            for (int mt = 0; mt < 4; mt++)
#pragma unroll
                for (int nt = 0; nt < 4; nt++) {
                    mma_bf16(acc[mt][nt], a[mt], bh[nt]);
                    mma_bf16(acc[mt][nt], a[mt], bl[nt]);
                }
#pragma unroll
            for (int mt = 0; mt < 4; mt++)
                ldsm4(a[mt], aLb + (uint32_t)(m0w + mt * 16 + a_r) * GSTRIDE + a_kb + kbo);
#pragma unroll
            for (int mt = 0; mt < 4; mt++)
#pragma unroll
                for (int nt = 0; nt < 4; nt++)
                    mma_bf16(acc[mt][nt], a[mt], bh[nt]);
        }
    }

    float* gout = &g_gramp[ks][n][0][0];
#pragma unroll
    for (int mt = 0; mt < 4; mt++)
#pragma unroll
        for (int h = 0; h < 2; h++) {
            const int c = c0 + m0w + mt * 16 + (lane >> 2) + h * 8;
#pragma unroll
            for (int nt = 0; nt < 4; nt++) {
                const int d = d0 + n0w + nt * 8 + (lane & 3) * 2;
                const float v0 = acc[mt][nt][h * 2], v1 = acc[mt][nt][h * 2 + 1];
                *(float2*)(gout + (size_t)c * CC + d) = make_float2(v0, v1);
                if (!diag) {
                    gout[(size_t)d * CC + c] = v0;
                    gout[(size_t)(d + 1) * CC + c] = v1;
                }
            }
        }
}

// ---- t7^T packed (split bf16, pre-scaled by 1/896) ---------------------------
__global__ void k_t7(const float* __restrict__ Wg1, const float* __restrict__ bg1,
                     const float* __restrict__ Wg2, const float* __restrict__ bg2,
                     const float* __restrict__ p7w) {
    __shared__ float W1s[32][33], W2s[32][33], Gs[32][33], Ms[32][33];
    const int n = blockIdx.z, g = blockIdx.y, h = blockIdx.x;
    const int tx = threadIdx.x, ty = threadIdx.y;

    W1s[ty][tx] = Wg1[(g * 32 + ty) * 32 + tx];
    W2s[ty][tx] = Wg2[(h * 32 + ty) * 32 + tx];
    Gs[ty][tx]  = g_gramp[0][n][g * 32 + ty][h * 32 + tx]
                + g_gramp[1][n][g * 32 + ty][h * 32 + tx]
                + g_gramp[2][n][g * 32 + ty][h * 32 + tx];
    __syncthreads();

    float m = 0.f;
#pragma unroll
    for (int i = 0; i < 32; i++) m += W1s[ty][i] * Gs[i][tx];
    Ms[ty][tx] = m;
    __syncthreads();

    float t5 = 0.f;
#pragma unroll
    for (int j = 0; j < 32; j++) t5 += Ms[ty][j] * W2s[tx][j];

    const int c = g * 32 + ty, d = h * 32 + tx;
    const float b1 = bg1[c], b2 = bg2[d];
    t5 += b1 * g_v[n][d] + g_u[n][c] * b2 + (float)HW * b1 * b2;
    const float val = p7w[c * 256 + d] * t5 * (1.0f / 896.0f);

    __syncthreads();
    W1s[ty][tx] = val;
    __syncthreads();
    const float tv = W1s[tx][ty];          // t7[c=g*32+tx][d=h*32+ty]
    const int dd = h * 32 + ty, cc = g * 32 + tx;
    __nv_bfloat16 hh = __float2bfloat16(tv);
    g_t7k[n][0][cc >> 4][dd * 24 + (cc & 15)] = hh;
    g_t7k[n][1][cc >> 4][dd * 24 + (cc & 15)] =
        __float2bfloat16(tv - __bfloat162float(hh));
}

// ---- fused: bulk A (3-deep) + bulk B rows, N=128, 512 threads ----------------
#define BROW 272u
#define BHALF 69632u
#define FACH 12288u
#define AOFF (2u * BHALF)
#define FUSED_SMEM (2 * 69632 + 6 * 12288)   // 212992
#define ACHB 24576u

__global__ __launch_bounds__(512, 1) void k_fused(const float* __restrict__ bp3,
                                                  float* __restrict__ out) {
    extern __shared__ char sm[];
    __shared__ alignas(8) uint64_t s_mb[4];   // A0, A1, A2, B
    const int n = blockIdx.y, sx = blockIdx.x;
    const int tid = threadIdx.x, lane = tid & 31, wid = tid >> 5;
    const int m0w = (wid >> 2) * 64, n0w = (wid & 3) * 32;
    const uint32_t smb = smem_u32(sm);
    const uint32_t mbA0 = smem_u32(&s_mb[0]);
    const uint32_t mbA1 = mbA0 + 8, mbA2 = mbA0 + 16, mbB = mbA0 + 24;
    const bool tail = (sx == 24);
    const uint32_t browbytes = tail ? 128u : 256u;

    auto issueA = [&](int g1, int buf) {   // single thread
        const char* Ah = (g1 < 16) ? (const char*)&g_wpk[0][g1 & 15][0]
                                   : (const char*)&g_t7k[n][0][g1 & 15][0];
        const char* Al = (g1 < 16) ? (const char*)&g_wpk[1][g1 & 15][0]
                                   : (const char*)&g_t7k[n][1][g1 & 15][0];
        const uint32_t mb = (buf == 0) ? mbA0 : (buf == 1) ? mbA1 : mbA2;
        MBAR_EXPECT(mb, ACHB);
        bulkcp(smb + AOFF + (buf * 2 + 0) * FACH, Ah, FACH, mb);
        bulkcp(smb + AOFF + (buf * 2 + 1) * FACH, Al, FACH, mb);
    };

    if (tid == 0) {
        MBAR_INIT(mbA0, 1); MBAR_INIT(mbA1, 1); MBAR_INIT(mbA2, 1); MBAR_INIT(mbB, 1);
    }
    __syncthreads();
    if (tid == 0) {
        MBAR_EXPECT(mbB, 512u * browbytes);
        issueA(0, 0);
        issueA(1, 1);
    }
    __syncthreads();
    {   // B: 256 rows x (hi,lo), one bulk per row
        const int half = tid >> 8, r = tid & 255;
        const char* src = (half ? (const char*)&g_xl[n][r][0]
                                : (const char*)&g_xh[n][r][0]) + (size_t)sx * 256;
        bulkcp(smb + half * BHALF + (uint32_t)r * BROW, src, browbytes, mbB);
    }

    float acc[4][4][4];
#pragma unroll
    for (int i = 0; i < 4; i++)
#pragma unroll
        for (int j = 0; j < 4; j++)
#pragma unroll
            for (int p = 0; p < 4; p++) acc[i][j][p] = 0.f;

    const int a_r = lane & 15, a_kb = (lane >> 4) * 16;
    const int bt_r = (lane & 7) + 8 * ((lane >> 3) & 1);
    const int bt_nb = (lane >> 4) * 16;
    int pa0 = 0, pa1 = 0, pa2 = 0;

    for (int g = 0; g < 32; g++) {
        const int buf = g % 3;
        __syncthreads();                           // buffer (g+2)%3 free now
        if (g + 2 < 32 && tid == 0) issueA(g + 2, (g + 2) % 3);
        if (buf == 0)      { MBAR_WAIT(mbA0, pa0); pa0 ^= 1; }
        else if (buf == 1) { MBAR_WAIT(mbA1, pa1); pa1 ^= 1; }
        else               { MBAR_WAIT(mbA2, pa2); pa2 ^= 1; }
        if (g == 0) MBAR_WAIT(mbB, 0);

        if (g == 16) {
            // stage0 epilogue: t6 = max(t3 + bias, sin(pi/2 x)); rewrite B
#pragma unroll
            for (int mt = 0; mt < 4; mt++)
#pragma unroll
                for (int h = 0; h < 2; h++) {
                    const int c = m0w + mt * 16 + (lane >> 2) + h * 8;
                    const float bias = __ldg(&bp3[c]);
#pragma unroll
                    for (int nt = 0; nt < 4; nt++) {
                        const int j = n0w + nt * 8 + (lane & 3) * 2;
                        uint32_t* ph = (uint32_t*)(sm + (uint32_t)c * BROW + j * 2);
                        uint32_t* pl = (uint32_t*)(sm + BHALF + (uint32_t)c * BROW + j * 2);
                        const uint32_t vh = *ph, vl = *pl;
                        const float x0 = bflo(vh) + bflo(vl);
                        const float x1 = bfhi(vh) + bfhi(vl);
                        const float t60 = fmaxf(acc[mt][nt][h * 2] + bias,
                                                __sinf(PI_HALF * x0));
                        const float t61 = fmaxf(acc[mt][nt][h * 2 + 1] + bias,
                                                __sinf(PI_HALF * x1));
                        __nv_bfloat16 h0 = __float2bfloat16(t60);
                        __nv_bfloat16 h1 = __float2bfloat16(t61);
                        *ph = pk2(h0, h1);
                        *pl = pk2(__float2bfloat16(t60 - __bfloat162float(h0)),
                                  __float2bfloat16(t61 - __bfloat162float(h1)));
                        acc[mt][nt][h * 2] = 0.f;
                        acc[mt][nt][h * 2 + 1] = 0.f;
                    }
                }
            __syncthreads();
        }

        const uint32_t aHb = smb + AOFF + (buf * 2 + 0) * FACH;
        const uint32_t aLb = smb + AOFF + (buf * 2 + 1) * FACH;
        const int kg = (g & 15) * 16;
        uint32_t a[4][4], bh[4][2], bl[4][2];
#pragma unroll
        for (int mt = 0; mt < 4; mt++)
            ldsm4(a[mt], aHb + (uint32_t)(m0w + mt * 16 + a_r) * 48u + a_kb);
#pragma unroll
        for (int nt2 = 0; nt2 < 2; nt2++) {
            const uint32_t ro = (uint32_t)(kg + bt_r) * BROW
                              + (uint32_t)(n0w + nt2 * 16) * 2 + bt_nb;
            uint32_t t[4];
            ldsm4t(t, smb + ro);
            bh[nt2 * 2][0] = t[0]; bh[nt2 * 2][1] = t[1];
            bh[nt2 * 2 + 1][0] = t[2]; bh[nt2 * 2 + 1][1] = t[3];
            ldsm4t(t, smb + BHALF + ro);
            bl[nt2 * 2][0] = t[0]; bl[nt2 * 2][1] = t[1];
            bl[nt2 * 2 + 1][0] = t[2]; bl[nt2 * 2 + 1][1] = t[3];
        }
#pragma unroll
        for (int mt = 0; mt < 4; mt++)
#pragma unroll
            for (int nt = 0; nt < 4; nt++) {
                mma_bf16(acc[mt][nt], a[mt], bh[nt]);
                mma_bf16(acc[mt][nt], a[mt], bl[nt]);
            }
#pragma unroll
        for (int mt = 0; mt < 4; mt++)
            ldsm4(a[mt], aLb + (uint32_t)(m0w + mt * 16 + a_r) * 48u + a_kb);
#pragma unroll
        for (int mt = 0; mt < 4; mt++)
#pragma unroll
            for (int nt = 0; nt < 4; nt++)
                mma_bf16(acc[mt][nt], a[mt], bh[nt]);
    }

    float* ob = out + (size_t)n * CC * HW + (size_t)sx * 128;
#pragma unroll
    for (int mt = 0; mt < 4; mt++)
#pragma unroll
        for (int h = 0; h < 2; h++) {
            const int d = m0w + mt * 16 + (lane >> 2) + h * 8;
#pragma unroll
            for (int nt = 0; nt < 4; nt++) {
                const int j = n0w + nt * 8 + (lane & 3) * 2;
                if (!tail || j < 64)
                    *(float2*)(ob + (size_t)d * HW + j) =
                        make_float2(acc[mt][nt][h * 2], acc[mt][nt][h * 2 + 1]);
            }
        }
}

extern "C" void kernel_launch(void* const* d_in, const int* in_sizes, int n_in,
                              void* d_out, int out_size) {
    (void)in_sizes; (void)n_in; (void)out_size;
    const float* x   = (const float*)d_in[0];
    const float* Wp3 = (const float*)d_in[1];
    const float* bp3 = (const float*)d_in[2];
    const float* Wg1 = (const float*)d_in[3];
    const float* bg1 = (const float*)d_in[4];
    const float* Wg2 = (const float*)d_in[5];
    const float* bg2 = (const float*)d_in[6];
    const float* p7w = (const float*)d_in[7];
    float* out = (float*)d_out;

    cudaFuncSetAttribute(k_gram,  cudaFuncAttributeMaxDynamicSharedMemorySize, GRAM_SMEM);
    cudaFuncSetAttribute(k_fused, cudaFuncAttributeMaxDynamicSharedMemorySize, FUSED_SMEM);

    k_wprep<<<256, 256>>>(Wp3);
    k_prep<<<dim3(256, 32), 256>>>(x);
    k_uv<<<32, 256>>>(Wg1, Wg2);
    k_gram<<<dim3(3, 32, 3), 256, GRAM_SMEM>>>();
    k_t7<<<dim3(8, 8, 32), dim3(32, 32)>>>(Wg1, bg1, Wg2, bg2, p7w);
    k_fused<<<dim3(25, 32), 512, FUSED_SMEM>>>(bp3, out);
}

// round 16
// speedup vs baseline: 1.0586x; 1.0586x over previous
#include <cuda_runtime.h>
#include <cuda_bf16.h>
#include <stdint.h>
#include <math.h>

#define NB 32
#define CC 256
#define HW 3136
#define PI_HALF 1.57079632679489662f

// packed x: [n][chunk of 32 spatial][hi/lo][256 ch * 40 bf16 (32 data + 8 pad)]
__device__ __nv_bfloat16 g_xgk[NB][98][2][256 * 40];
__device__ float g_gramp[3][NB][CC][CC];
__device__ float g_rowsum[NB][CC];
__device__ float g_u[NB][CC];
__device__ float g_v[NB][CC];
__device__ __nv_bfloat16 g_wpk[2][16][256 * 24];       // packed Wp3 (48B rows)
__device__ __nv_bfloat16 g_t7k[NB][2][16][256 * 24];   // packed t7^T (48B rows)

__device__ __forceinline__ uint32_t smem_u32(const void* p) {
    uint32_t a;
    asm("{ .reg .u64 t; cvta.to.shared.u64 t, %1; cvt.u32.u64 %0, t; }"
        : "=r"(a) : "l"(p));
    return a;
}
__device__ __forceinline__ void bulkcp(uint32_t dst, const void* src,
                                       uint32_t bytes, uint32_t mbar) {
    asm volatile(
        "cp.async.bulk.shared::cta.global.mbarrier::complete_tx::bytes "
        "[%0], [%1], %2, [%3];"
        :: "r"(dst), "l"(src), "r"(bytes), "r"(mbar) : "memory");
}
#define MBAR_INIT(a, c) asm volatile("mbarrier.init.shared.b64 [%0], %1;" :: "r"(a), "r"((uint32_t)(c)) : "memory")
#define MBAR_EXPECT(a, b) asm volatile("mbarrier.arrive.expect_tx.shared.b64 _, [%0], %1;" :: "r"(a), "r"((uint32_t)(b)) : "memory")
#define MBAR_WAIT(a, ph) do {                                                   \
    uint32_t _m = (a), _p = (uint32_t)(ph), _d;                                 \
    asm volatile("{\n\t.reg .pred p;\n\t"                                       \
        "mbarrier.try_wait.parity.acquire.cta.shared::cta.b64 p, [%1], %2;\n\t" \
        "selp.b32 %0, 1, 0, p;\n\t}" : "=r"(_d) : "r"(_m), "r"(_p) : "memory"); \
    if (!_d) { asm volatile("{\n\t.reg .pred P1;\n\tWL_%=:\n\t"                 \
        "mbarrier.try_wait.parity.acquire.cta.shared::cta.b64 P1, [%0], %1, 0x989680;\n\t" \
        "@P1 bra.uni WD_%=;\n\tbra.uni WL_%=;\n\tWD_%=:\n\t}"                   \
        :: "r"(_m), "r"(_p) : "memory"); }                                      \
} while (0)

__device__ __forceinline__ void ldsm4(uint32_t r[4], uint32_t a) {
    asm volatile("ldmatrix.sync.aligned.m8n8.x4.shared.b16 {%0,%1,%2,%3}, [%4];"
                 : "=r"(r[0]), "=r"(r[1]), "=r"(r[2]), "=r"(r[3]) : "r"(a));
}
__device__ __forceinline__ void ldsm4t(uint32_t r[4], uint32_t a) {
    asm volatile("ldmatrix.sync.aligned.m8n8.x4.trans.shared.b16 {%0,%1,%2,%3}, [%4];"
                 : "=r"(r[0]), "=r"(r[1]), "=r"(r[2]), "=r"(r[3]) : "r"(a));
}
__device__ __forceinline__ void mma_bf16(float c[4], const uint32_t a[4],
                                         const uint32_t b[2]) {
    asm volatile(
        "mma.sync.aligned.m16n8k16.row.col.f32.bf16.bf16.f32 "
        "{%0,%1,%2,%3}, {%4,%5,%6,%7}, {%8,%9}, {%0,%1,%2,%3};"
        : "+f"(c[0]), "+f"(c[1]), "+f"(c[2]), "+f"(c[3])
        : "r"(a[0]), "r"(a[1]), "r"(a[2]), "r"(a[3]), "r"(b[0]), "r"(b[1]));
}
__device__ __forceinline__ uint32_t pk2(__nv_bfloat16 a, __nv_bfloat16 b) {
    unsigned short ua = *(unsigned short*)&a, ub = *(unsigned short*)&b;
    return (uint32_t)ua | ((uint32_t)ub << 16);
}
__device__ __forceinline__ float bflo(uint32_t v) {
    unsigned short u = (unsigned short)(v & 0xffffu);
    return __bfloat162float(*(__nv_bfloat16*)&u);
}
__device__ __forceinline__ float bfhi(uint32_t v) {
    unsigned short u = (unsigned short)(v >> 16);
    return __bfloat162float(*(__nv_bfloat16*)&u);
}

// ---- prep: x -> packed bf16 hi/lo chunks + rowsums ---------------------------
__global__ void k_prep(const float* __restrict__ x) {
    const int n = blockIdx.y, c = blockIdx.x, t = threadIdx.x;
    const float4* row = (const float4*)(x + ((size_t)n * CC + c) * HW);
    float s = 0.f;
    for (int u = t; u < HW / 4; u += 256) {
        float4 v = row[u];
        s += v.x + v.y + v.z + v.w;
        __nv_bfloat16 h0 = __float2bfloat16(v.x), h1 = __float2bfloat16(v.y);
        __nv_bfloat16 h2 = __float2bfloat16(v.z), h3 = __float2bfloat16(v.w);
        uint2 ph, pl;
        ph.x = pk2(h0, h1); ph.y = pk2(h2, h3);
        pl.x = pk2(__float2bfloat16(v.x - __bfloat162float(h0)),
                   __float2bfloat16(v.y - __bfloat162float(h1)));
        pl.y = pk2(__float2bfloat16(v.z - __bfloat162float(h2)),
                   __float2bfloat16(v.w - __bfloat162float(h3)));
        char* pk = (char*)&g_xgk[n][u >> 3][0][0] + c * 80 + (u & 7) * 8;
        *(uint2*)pk = ph;
        *(uint2*)(pk + 20480) = pl;
    }
#pragma unroll
    for (int o = 16; o; o >>= 1) s += __shfl_down_sync(0xffffffffu, s, o);
    __shared__ float red[8];
    if ((t & 31) == 0) red[t >> 5] = s;
    __syncthreads();
    if (t == 0) {
        float tt = 0.f;
#pragma unroll
        for (int q = 0; q < 8; q++) tt += red[q];
        g_rowsum[n][c] = tt;
    }
}

__global__ void k_wprep(const float* __restrict__ w) {
    const int o = blockIdx.x, i = threadIdx.x;
    const float v = w[o * 256 + i];
    __nv_bfloat16 h = __float2bfloat16(v);
    g_wpk[0][i >> 4][o * 24 + (i & 15)] = h;
    g_wpk[1][i >> 4][o * 24 + (i & 15)] =
        __float2bfloat16(v - __bfloat162float(h));
}

__global__ void k_uv(const float* __restrict__ Wg1, const float* __restrict__ Wg2) {
    const int n = blockIdx.x, t = threadIdx.x;
    __shared__ float ss[256];
    ss[t] = g_rowsum[n][t];
    __syncthreads();
    const int g = t >> 5, r = t & 31;
    float u = 0.f, v = 0.f;
#pragma unroll
    for (int i = 0; i < 32; i++) {
        u += Wg1[(g * 32 + r) * 32 + i] * ss[g * 32 + i];
        v += Wg2[(g * 32 + r) * 32 + i] * ss[g * 32 + i];
    }
    g_u[n][t] = u;
    g_v[n][t] = v;
}

// ---- Gram = x x^T, bulk-copy chunks (round-15, unchanged) --------------------
#define GSTRIDE 80u
#define GCH 10240
#define GRAM_SMEM (8 * GCH)

__global__ __launch_bounds__(256, 2) void k_gram() {
    extern __shared__ char sm[];
    __shared__ alignas(8) uint64_t s_mb[2];
    const int q = blockIdx.x, n = blockIdx.y, ks = blockIdx.z;
    const int c0 = (q == 1) ? 128 : 0;
    const int d0 = (q == 0) ? 0 : 128;
    const bool diag = (q < 2);
    const int tid = threadIdx.x, lane = tid & 31, wid = tid >> 5;
    const int m0w = (wid & 1) * 64, n0w = (wid >> 1) * 32;
    const uint32_t smb = smem_u32(sm);
    const uint32_t mb0 = smem_u32(&s_mb[0]), mb1 = mb0 + 8;

    const int a_r = lane & 15, a_kb = (lane >> 4) * 16;
    const int b_r = (lane & 7) + 8 * (lane >> 4);
    const int b_kb = ((lane >> 3) & 1) * 16;

    float acc[4][4][4];
#pragma unroll
    for (int i = 0; i < 4; i++)
#pragma unroll
        for (int j = 0; j < 4; j++)
#pragma unroll
            for (int p = 0; p < 4; p++) acc[i][j][p] = 0.f;

    const int ck0 = ks * 33;
    const int nck = (ks < 2) ? 33 : 32;

    auto issueG = [&](int ci, int buf) {
        const uint32_t mb = buf ? mb1 : mb0;
        const char* base = (const char*)&g_xgk[n][ck0 + ci][0][0];
        MBAR_EXPECT(mb, diag ? 2 * GCH : 4 * GCH);
        bulkcp(smb + (buf * 2 + 0) * GCH, base + c0 * 80, GCH, mb);
        bulkcp(smb + (buf * 2 + 1) * GCH, base + 20480 + c0 * 80, GCH, mb);
        if (!diag) {
            bulkcp(smb + 4 * GCH + (buf * 2 + 0) * GCH, base + d0 * 80, GCH, mb);
            bulkcp(smb + 4 * GCH + (buf * 2 + 1) * GCH, base + 20480 + d0 * 80, GCH, mb);
        }
    };

    if (tid == 0) { MBAR_INIT(mb0, 1); MBAR_INIT(mb1, 1); }
    __syncthreads();
    if (tid == 0) issueG(0, 0);
    int ph0 = 0, ph1 = 0;

    for (int ci = 0; ci < nck; ci++) {
        const int buf = ci & 1;
        __syncthreads();
        if (ci < nck - 1 && tid == 0) issueG(ci + 1, buf ^ 1);
        if (buf == 0) { MBAR_WAIT(mb0, ph0); ph0 ^= 1; }
        else          { MBAR_WAIT(mb1, ph1); ph1 ^= 1; }

        const uint32_t aHb = smb + (buf * 2 + 0) * GCH;
        const uint32_t aLb = smb + (buf * 2 + 1) * GCH;
        const uint32_t bHb = diag ? aHb : smb + 4 * GCH + (buf * 2 + 0) * GCH;
        const uint32_t bLb = diag ? aLb : smb + 4 * GCH + (buf * 2 + 1) * GCH;
#pragma unroll
        for (int kk = 0; kk < 2; kk++) {
            const uint32_t kbo = kk * 32;
            uint32_t a[4][4], bh[4][2], bl[4][2];
#pragma unroll
            for (int mt = 0; mt < 4; mt++)
                ldsm4(a[mt], aHb + (uint32_t)(m0w + mt * 16 + a_r) * GSTRIDE + a_kb + kbo);
#pragma unroll
            for (int nt2 = 0; nt2 < 2; nt2++) {
                const uint32_t ro = (uint32_t)(n0w + nt2 * 16 + b_r) * GSTRIDE + b_kb + kbo;
                uint32_t t[4];
                ldsm4(t, bHb + ro);
                bh[nt2 * 2][0] = t[0]; bh[nt2 * 2][1] = t[1];
                bh[nt2 * 2 + 1][0] = t[2]; bh[nt2 * 2 + 1][1] = t[3];
                ldsm4(t, bLb + ro);
                bl[nt2 * 2][0] = t[0]; bl[nt2 * 2][1] = t[1];
                bl[nt2 * 2 + 1][0] = t[2]; bl[nt2 * 2 + 1][1] = t[3];
            }
#pragma unroll
            for (int mt = 0; mt < 4; mt++)
#pragma unroll
                for (int nt = 0; nt < 4; nt++) {
                    mma_bf16(acc[mt][nt], a[mt], bh[nt]);
                    mma_bf16(acc[mt][nt], a[mt], bl[nt]);
                }
#pragma unroll
            for (int mt = 0; mt < 4; mt++)
                ldsm4(a[mt], aLb + (uint32_t)(m0w + mt * 16 + a_r) * GSTRIDE + a_kb + kbo);
#pragma unroll
            for (int mt = 0; mt < 4; mt++)
#pragma unroll
                for (int nt = 0; nt < 4; nt++)
                    mma_bf16(acc[mt][nt], a[mt], bh[nt]);
        }
    }

    float* gout = &g_gramp[ks][n][0][0];
#pragma unroll
    for (int mt = 0; mt < 4; mt++)
#pragma unroll
        for (int h = 0; h < 2; h++) {
            const int c = c0 + m0w + mt * 16 + (lane >> 2) + h * 8;
#pragma unroll
            for (int nt = 0; nt < 4; nt++) {
                const int d = d0 + n0w + nt * 8 + (lane & 3) * 2;
                const float v0 = acc[mt][nt][h * 2], v1 = acc[mt][nt][h * 2 + 1];
                *(float2*)(gout + (size_t)c * CC + d) = make_float2(v0, v1);
                if (!diag) {
                    gout[(size_t)d * CC + c] = v0;
                    gout[(size_t)(d + 1) * CC + c] = v1;
                }
            }
        }
}

// ---- t7^T packed (split bf16, pre-scaled by 1/896) ---------------------------
__global__ void k_t7(const float* __restrict__ Wg1, const float* __restrict__ bg1,
                     const float* __restrict__ Wg2, const float* __restrict__ bg2,
                     const float* __restrict__ p7w) {
    __shared__ float W1s[32][33], W2s[32][33], Gs[32][33], Ms[32][33];
    const int n = blockIdx.z, g = blockIdx.y, h = blockIdx.x;
    const int tx = threadIdx.x, ty = threadIdx.y;

    W1s[ty][tx] = Wg1[(g * 32 + ty) * 32 + tx];
    W2s[ty][tx] = Wg2[(h * 32 + ty) * 32 + tx];
    Gs[ty][tx]  = g_gramp[0][n][g * 32 + ty][h * 32 + tx]
                + g_gramp[1][n][g * 32 + ty][h * 32 + tx]
                + g_gramp[2][n][g * 32 + ty][h * 32 + tx];
    __syncthreads();

    float m = 0.f;
#pragma unroll
    for (int i = 0; i < 32; i++) m += W1s[ty][i] * Gs[i][tx];
    Ms[ty][tx] = m;
    __syncthreads();

    float t5 = 0.f;
#pragma unroll
    for (int j = 0; j < 32; j++) t5 += Ms[ty][j] * W2s[tx][j];

    const int c = g * 32 + ty, d = h * 32 + tx;
    const float b1 = bg1[c], b2 = bg2[d];
    t5 += b1 * g_v[n][d] + g_u[n][c] * b2 + (float)HW * b1 * b2;
    const float val = p7w[c * 256 + d] * t5 * (1.0f / 896.0f);

    __syncthreads();
    W1s[ty][tx] = val;
    __syncthreads();
    const float tv = W1s[tx][ty];          // t7[c=g*32+tx][d=h*32+ty]
    const int dd = h * 32 + ty, cc = g * 32 + tx;
    __nv_bfloat16 hh = __float2bfloat16(tv);
    g_t7k[n][0][cc >> 4][dd * 24 + (cc & 15)] = hh;
    g_t7k[n][1][cc >> 4][dd * 24 + (cc & 15)] =
        __float2bfloat16(tv - __bfloat162float(hh));
}

// ---- fused: bulk A (2-deep) + bulk B chunks (packed), N=128, 512 thr ---------
#define BCHK 20480u               // one packed chunk half
#define B_LO 81920u               // lo panels base (4 * 20480)
#define AOFF 163840u
#define FACH 12288u
#define FUSED_SMEM (163840 + 4 * 12288)   // 212992
#define ACHB 24576u

__global__ __launch_bounds__(512, 1) void k_fused(const float* __restrict__ bp3,
                                                  float* __restrict__ out) {
    extern __shared__ char sm[];
    __shared__ alignas(8) uint64_t s_mb[3];   // A0, A1, B
    const int n = blockIdx.y, sx = blockIdx.x;
    const int tid = threadIdx.x, lane = tid & 31, wid = tid >> 5;
    const int m0w = (wid >> 2) * 64, n0w = (wid & 3) * 32;
    const uint32_t smb = smem_u32(sm);
    const uint32_t mbA0 = smem_u32(&s_mb[0]);
    const uint32_t mbA1 = mbA0 + 8, mbB = mbA0 + 16;
    const bool tail = (sx == 24);
    const int nchk = tail ? 2 : 4;

    auto issueA = [&](int g1, int buf) {   // single thread
        const char* Ah = (g1 < 16) ? (const char*)&g_wpk[0][g1 & 15][0]
                                   : (const char*)&g_t7k[n][0][g1 & 15][0];
        const char* Al = (g1 < 16) ? (const char*)&g_wpk[1][g1 & 15][0]
                                   : (const char*)&g_t7k[n][1][g1 & 15][0];
        const uint32_t mb = buf ? mbA1 : mbA0;
        MBAR_EXPECT(mb, ACHB);
        bulkcp(smb + AOFF + (buf * 2 + 0) * FACH, Ah, FACH, mb);
        bulkcp(smb + AOFF + (buf * 2 + 1) * FACH, Al, FACH, mb);
    };

    if (tid == 0) {
        MBAR_INIT(mbA0, 1); MBAR_INIT(mbA1, 1); MBAR_INIT(mbB, 1);
    }
    __syncthreads();
    if (tid == 0) {
        MBAR_EXPECT(mbB, (uint32_t)nchk * 2u * BCHK);
        for (int p = 0; p < nchk; p++) {
            const char* base = (const char*)&g_xgk[n][4 * sx + p][0][0];
            bulkcp(smb + p * BCHK, base, BCHK, mbB);
            bulkcp(smb + B_LO + p * BCHK, base + BCHK, BCHK, mbB);
        }
        issueA(0, 0);
    }

    float acc[4][4][4];
#pragma unroll
    for (int i = 0; i < 4; i++)
#pragma unroll
        for (int j = 0; j < 4; j++)
#pragma unroll
            for (int p = 0; p < 4; p++) acc[i][j][p] = 0.f;

    const int a_r = lane & 15, a_kb = (lane >> 4) * 16;
    const int bt_r = (lane & 7) + 8 * ((lane >> 3) & 1);
    const int bt_nb = (lane >> 4) * 16;
    int pa0 = 0, pa1 = 0;

    for (int g = 0; g < 32; g++) {
        const int buf = g & 1;
        __syncthreads();
        if (g < 31 && tid == 0) issueA(g + 1, buf ^ 1);
        if (buf == 0) { MBAR_WAIT(mbA0, pa0); pa0 ^= 1; }
        else          { MBAR_WAIT(mbA1, pa1); pa1 ^= 1; }
        if (g == 0) MBAR_WAIT(mbB, 0);

        if (g == 16) {
            // stage0 epilogue: t6 = max(t3 + bias, sin(pi/2 x)); rewrite B
#pragma unroll
            for (int mt = 0; mt < 4; mt++)
#pragma unroll
                for (int h = 0; h < 2; h++) {
                    const int c = m0w + mt * 16 + (lane >> 2) + h * 8;
                    const float bias = __ldg(&bp3[c]);
#pragma unroll
                    for (int nt = 0; nt < 4; nt++) {
                        const int j = n0w + nt * 8 + (lane & 3) * 2;
                        const uint32_t off = (uint32_t)(j >> 5) * BCHK
                                           + (uint32_t)c * 80u + (j & 31) * 2;
                        uint32_t* ph = (uint32_t*)(sm + off);
                        uint32_t* pl = (uint32_t*)(sm + B_LO + off);
                        const uint32_t vh = *ph, vl = *pl;
                        const float x0 = bflo(vh) + bflo(vl);
                        const float x1 = bfhi(vh) + bfhi(vl);
                        const float t60 = fmaxf(acc[mt][nt][h * 2] + bias,
                                                __sinf(PI_HALF * x0));
                        const float t61 = fmaxf(acc[mt][nt][h * 2 + 1] + bias,
                                                __sinf(PI_HALF * x1));
                        __nv_bfloat16 h0 = __float2bfloat16(t60);
                        __nv_bfloat16 h1 = __float2bfloat16(t61);
                        *ph = pk2(h0, h1);
                        *pl = pk2(__float2bfloat16(t60 - __bfloat162float(h0)),
                                  __float2bfloat16(t61 - __bfloat162float(h1)));
                        acc[mt][nt][h * 2] = 0.f;
                        acc[mt][nt][h * 2 + 1] = 0.f;
                    }
                }
            __syncthreads();
        }

        const uint32_t aHb = smb + AOFF + (buf * 2 + 0) * FACH;
        const uint32_t aLb = smb + AOFF + (buf * 2 + 1) * FACH;
        const int kg = (g & 15) * 16;
        uint32_t a[4][4], bh[4][2], bl[4][2];
#pragma unroll
        for (int mt = 0; mt < 4; mt++)
            ldsm4(a[mt], aHb + (uint32_t)(m0w + mt * 16 + a_r) * 48u + a_kb);
#pragma unroll
        for (int nt2 = 0; nt2 < 2; nt2++) {
            const int jcol = n0w + nt2 * 16;
            const uint32_t ro = (uint32_t)(jcol >> 5) * BCHK
                              + (uint32_t)(kg + bt_r) * 80u
                              + (jcol & 31) * 2 + bt_nb;
            uint32_t t[4];
            ldsm4t(t, smb + ro);
            bh[nt2 * 2][0] = t[0]; bh[nt2 * 2][1] = t[1];
            bh[nt2 * 2 + 1][0] = t[2]; bh[nt2 * 2 + 1][1] = t[3];
            ldsm4t(t, smb + B_LO + ro);
            bl[nt2 * 2][0] = t[0]; bl[nt2 * 2][1] = t[1];
            bl[nt2 * 2 + 1][0] = t[2]; bl[nt2 * 2 + 1][1] = t[3];
        }
#pragma unroll
        for (int mt = 0; mt < 4; mt++)
#pragma unroll
            for (int nt = 0; nt < 4; nt++) {
                mma_bf16(acc[mt][nt], a[mt], bh[nt]);
                mma_bf16(acc[mt][nt], a[mt], bl[nt]);
            }
#pragma unroll
        for (int mt = 0; mt < 4; mt++)
            ldsm4(a[mt], aLb + (uint32_t)(m0w + mt * 16 + a_r) * 48u + a_kb);
#pragma unroll
        for (int mt = 0; mt < 4; mt++)
#pragma unroll
            for (int nt = 0; nt < 4; nt++)
                mma_bf16(acc[mt][nt], a[mt], bh[nt]);
    }

    float* ob = out + (size_t)n * CC * HW + (size_t)sx * 128;
#pragma unroll
    for (int mt = 0; mt < 4; mt++)
#pragma unroll
        for (int h = 0; h < 2; h++) {
            const int d = m0w + mt * 16 + (lane >> 2) + h * 8;
#pragma unroll
            for (int nt = 0; nt < 4; nt++) {
                const int j = n0w + nt * 8 + (lane & 3) * 2;
                if (!tail || j < 64)
                    *(float2*)(ob + (size_t)d * HW + j) =
                        make_float2(acc[mt][nt][h * 2], acc[mt][nt][h * 2 + 1]);
            }
        }
}

extern "C" void kernel_launch(void* const* d_in, const int* in_sizes, int n_in,
                              void* d_out, int out_size) {
    (void)in_sizes; (void)n_in; (void)out_size;
    const float* x   = (const float*)d_in[0];
    const float* Wp3 = (const float*)d_in[1];
    const float* bp3 = (const float*)d_in[2];
    const float* Wg1 = (const float*)d_in[3];
    const float* bg1 = (const float*)d_in[4];
    const float* Wg2 = (const float*)d_in[5];
    const float* bg2 = (const float*)d_in[6];
    const float* p7w = (const float*)d_in[7];
    float* out = (float*)d_out;

    cudaFuncSetAttribute(k_gram,  cudaFuncAttributeMaxDynamicSharedMemorySize, GRAM_SMEM);
    cudaFuncSetAttribute(k_fused, cudaFuncAttributeMaxDynamicSharedMemorySize, FUSED_SMEM);

    k_wprep<<<256, 256>>>(Wp3);
    k_prep<<<dim3(256, 32), 256>>>(x);
    k_uv<<<32, 256>>>(Wg1, Wg2);
    k_gram<<<dim3(3, 32, 3), 256, GRAM_SMEM>>>();
    k_t7<<<dim3(8, 8, 32), dim3(32, 32)>>>(Wg1, bg1, Wg2, bg2, p7w);
    k_fused<<<dim3(25, 32), 512, FUSED_SMEM>>>(bp3, out);
}

// round 17
// speedup vs baseline: 1.1213x; 1.0592x over previous
#include <cuda_runtime.h>
#include <cuda_bf16.h>
#include <stdint.h>
#include <math.h>

#define NB 32
#define CC 256
#define HW 3136
#define PI_HALF 1.57079632679489662f

// packed x: [n][chunk of 32 spatial][hi/lo][256 ch * 40 bf16 (32 data + 8 pad)]
__device__ __nv_bfloat16 g_xgk[NB][98][2][256 * 40];
__device__ float g_gramp[3][NB][CC][CC];
__device__ float g_rowsum[NB][CC];
__device__ float g_u[NB][CC];
__device__ float g_v[NB][CC];
__device__ __nv_bfloat16 g_wpk[2][16][256 * 24];       // packed Wp3 (48B rows)
__device__ __nv_bfloat16 g_t7k[NB][2][16][256 * 24];   // packed t7^T (48B rows)

__device__ __forceinline__ uint32_t smem_u32(const void* p) {
    uint32_t a;
    asm("{ .reg .u64 t; cvta.to.shared.u64 t, %1; cvt.u32.u64 %0, t; }"
        : "=r"(a) : "l"(p));
    return a;
}
__device__ __forceinline__ void bulkcp(uint32_t dst, const void* src,
                                       uint32_t bytes, uint32_t mbar) {
    asm volatile(
        "cp.async.bulk.shared::cta.global.mbarrier::complete_tx::bytes "
        "[%0], [%1], %2, [%3];"
        :: "r"(dst), "l"(src), "r"(bytes), "r"(mbar) : "memory");
}
#define MBAR_INIT(a, c) asm volatile("mbarrier.init.shared.b64 [%0], %1;" :: "r"(a), "r"((uint32_t)(c)) : "memory")
#define MBAR_EXPECT(a, b) asm volatile("mbarrier.arrive.expect_tx.shared.b64 _, [%0], %1;" :: "r"(a), "r"((uint32_t)(b)) : "memory")
#define MBAR_ARRIVE(a) asm volatile("mbarrier.arrive.shared.b64 _, [%0];" :: "r"(a) : "memory")
#define MBAR_WAIT(a, ph) do {                                                   \
    uint32_t _m = (a), _p = (uint32_t)(ph), _d;                                 \
    asm volatile("{\n\t.reg .pred p;\n\t"                                       \
        "mbarrier.try_wait.parity.acquire.cta.shared::cta.b64 p, [%1], %2;\n\t" \
        "selp.b32 %0, 1, 0, p;\n\t}" : "=r"(_d) : "r"(_m), "r"(_p) : "memory"); \
    if (!_d) { asm volatile("{\n\t.reg .pred P1;\n\tWL_%=:\n\t"                 \
        "mbarrier.try_wait.parity.acquire.cta.shared::cta.b64 P1, [%0], %1, 0x989680;\n\t" \
        "@P1 bra.uni WD_%=;\n\tbra.uni WL_%=;\n\tWD_%=:\n\t}"                   \
        :: "r"(_m), "r"(_p) : "memory"); }                                      \
} while (0)

__device__ __forceinline__ void ldsm4(uint32_t r[4], uint32_t a) {
    asm volatile("ldmatrix.sync.aligned.m8n8.x4.shared.b16 {%0,%1,%2,%3}, [%4];"
                 : "=r"(r[0]), "=r"(r[1]), "=r"(r[2]), "=r"(r[3]) : "r"(a));
}
__device__ __forceinline__ void ldsm4t(uint32_t r[4], uint32_t a) {
    asm volatile("ldmatrix.sync.aligned.m8n8.x4.trans.shared.b16 {%0,%1,%2,%3}, [%4];"
                 : "=r"(r[0]), "=r"(r[1]), "=r"(r[2]), "=r"(r[3]) : "r"(a));
}
__device__ __forceinline__ void mma_bf16(float c[4], const uint32_t a[4],
                                         const uint32_t b[2]) {
    asm volatile(
        "mma.sync.aligned.m16n8k16.row.col.f32.bf16.bf16.f32 "
        "{%0,%1,%2,%3}, {%4,%5,%6,%7}, {%8,%9}, {%0,%1,%2,%3};"
        : "+f"(c[0]), "+f"(c[1]), "+f"(c[2]), "+f"(c[3])
        : "r"(a[0]), "r"(a[1]), "r"(a[2]), "r"(a[3]), "r"(b[0]), "r"(b[1]));
}
__device__ __forceinline__ uint32_t pk2(__nv_bfloat16 a, __nv_bfloat16 b) {
    unsigned short ua = *(unsigned short*)&a, ub = *(unsigned short*)&b;
    return (uint32_t)ua | ((uint32_t)ub << 16);
}
__device__ __forceinline__ float bflo(uint32_t v) {
    unsigned short u = (unsigned short)(v & 0xffffu);
    return __bfloat162float(*(__nv_bfloat16*)&u);
}
__device__ __forceinline__ float bfhi(uint32_t v) {
    unsigned short u = (unsigned short)(v >> 16);
    return __bfloat162float(*(__nv_bfloat16*)&u);
}

// ---- prep: x -> packed bf16 hi/lo chunks (16B stores) + rowsums --------------
__global__ void k_prep(const float* __restrict__ x) {
    const int n = blockIdx.y, c = blockIdx.x, t = threadIdx.x;
    const float4* row = (const float4*)(x + ((size_t)n * CC + c) * HW);
    float s = 0.f;
    for (int u2 = t; u2 < HW / 8; u2 += 256) {   // handles spatial [8*u2, 8*u2+8)
        const int u = 2 * u2;
        float4 v0 = row[u], v1 = row[u + 1];
        s += v0.x + v0.y + v0.z + v0.w + v1.x + v1.y + v1.z + v1.w;
        __nv_bfloat16 h0 = __float2bfloat16(v0.x), h1 = __float2bfloat16(v0.y);
        __nv_bfloat16 h2 = __float2bfloat16(v0.z), h3 = __float2bfloat16(v0.w);
        __nv_bfloat16 h4 = __float2bfloat16(v1.x), h5 = __float2bfloat16(v1.y);
        __nv_bfloat16 h6 = __float2bfloat16(v1.z), h7 = __float2bfloat16(v1.w);
        uint4 ph, pl;
        ph.x = pk2(h0, h1); ph.y = pk2(h2, h3);
        ph.z = pk2(h4, h5); ph.w = pk2(h6, h7);
        pl.x = pk2(__float2bfloat16(v0.x - __bfloat162float(h0)),
                   __float2bfloat16(v0.y - __bfloat162float(h1)));
        pl.y = pk2(__float2bfloat16(v0.z - __bfloat162float(h2)),
                   __float2bfloat16(v0.w - __bfloat162float(h3)));
        pl.z = pk2(__float2bfloat16(v1.x - __bfloat162float(h4)),
                   __float2bfloat16(v1.y - __bfloat162float(h5)));
        pl.w = pk2(__float2bfloat16(v1.z - __bfloat162float(h6)),
                   __float2bfloat16(v1.w - __bfloat162float(h7)));
        char* pk = (char*)&g_xgk[n][u >> 3][0][0] + c * 80 + (u & 7) * 8;
        *(uint4*)pk = ph;
        *(uint4*)(pk + 20480) = pl;
    }
#pragma unroll
    for (int o = 16; o; o >>= 1) s += __shfl_down_sync(0xffffffffu, s, o);
    __shared__ float red[8];
    if ((t & 31) == 0) red[t >> 5] = s;
    __syncthreads();
    if (t == 0) {
        float tt = 0.f;
#pragma unroll
        for (int q = 0; q < 8; q++) tt += red[q];
        g_rowsum[n][c] = tt;
    }
}

__global__ void k_wprep(const float* __restrict__ w) {
    const int o = blockIdx.x, i = threadIdx.x;
    const float v = w[o * 256 + i];
    __nv_bfloat16 h = __float2bfloat16(v);
    g_wpk[0][i >> 4][o * 24 + (i & 15)] = h;
    g_wpk[1][i >> 4][o * 24 + (i & 15)] =
        __float2bfloat16(v - __bfloat162float(h));
}

__global__ void k_uv(const float* __restrict__ Wg1, const float* __restrict__ Wg2) {
    const int n = blockIdx.x, t = threadIdx.x;
    __shared__ float ss[256];
    ss[t] = g_rowsum[n][t];
    __syncthreads();
    const int g = t >> 5, r = t & 31;
    float u = 0.f, v = 0.f;
#pragma unroll
    for (int i = 0; i < 32; i++) {
        u += Wg1[(g * 32 + r) * 32 + i] * ss[g * 32 + i];
        v += Wg2[(g * 32 + r) * 32 + i] * ss[g * 32 + i];
    }
    g_u[n][t] = u;
    g_v[n][t] = v;
}

// ---- Gram = x x^T, bulk-copy chunks (round-15 form, unchanged) ---------------
#define GSTRIDE 80u
#define GCH 10240
#define GRAM_SMEM (8 * GCH)

__global__ __launch_bounds__(256, 2) void k_gram() {
    extern __shared__ char sm[];
    __shared__ alignas(8) uint64_t s_mb[2];
    const int q = blockIdx.x, n = blockIdx.y, ks = blockIdx.z;
    const int c0 = (q == 1) ? 128 : 0;
    const int d0 = (q == 0) ? 0 : 128;
    const bool diag = (q < 2);
    const int tid = threadIdx.x, lane = tid & 31, wid = tid >> 5;
    const int m0w = (wid & 1) * 64, n0w = (wid >> 1) * 32;
    const uint32_t smb = smem_u32(sm);
    const uint32_t mb0 = smem_u32(&s_mb[0]), mb1 = mb0 + 8;

    const int a_r = lane & 15, a_kb = (lane >> 4) * 16;
    const int b_r = (lane & 7) + 8 * (lane >> 4);
    const int b_kb = ((lane >> 3) & 1) * 16;

    float acc[4][4][4];
#pragma unroll
    for (int i = 0; i < 4; i++)
#pragma unroll
        for (int j = 0; j < 4; j++)
#pragma unroll
            for (int p = 0; p < 4; p++) acc[i][j][p] = 0.f;

    const int ck0 = ks * 33;
    const int nck = (ks < 2) ? 33 : 32;

    auto issueG = [&](int ci, int buf) {
        const uint32_t mb = buf ? mb1 : mb0;
        const char* base = (const char*)&g_xgk[n][ck0 + ci][0][0];
        MBAR_EXPECT(mb, diag ? 2 * GCH : 4 * GCH);
        bulkcp(smb + (buf * 2 + 0) * GCH, base + c0 * 80, GCH, mb);
        bulkcp(smb + (buf * 2 + 1) * GCH, base + 20480 + c0 * 80, GCH, mb);
        if (!diag) {
            bulkcp(smb + 4 * GCH + (buf * 2 + 0) * GCH, base + d0 * 80, GCH, mb);
            bulkcp(smb + 4 * GCH + (buf * 2 + 1) * GCH, base + 20480 + d0 * 80, GCH, mb);
        }
    };

    if (tid == 0) { MBAR_INIT(mb0, 1); MBAR_INIT(mb1, 1); }
    __syncthreads();
    if (tid == 0) issueG(0, 0);
    int ph0 = 0, ph1 = 0;

    for (int ci = 0; ci < nck; ci++) {
        const int buf = ci & 1;
        __syncthreads();
        if (ci < nck - 1 && tid == 0) issueG(ci + 1, buf ^ 1);
        if (buf == 0) { MBAR_WAIT(mb0, ph0); ph0 ^= 1; }
        else          { MBAR_WAIT(mb1, ph1); ph1 ^= 1; }

        const uint32_t aHb = smb + (buf * 2 + 0) * GCH;
        const uint32_t aLb = smb + (buf * 2 + 1) * GCH;
        const uint32_t bHb = diag ? aHb : smb + 4 * GCH + (buf * 2 + 0) * GCH;
        const uint32_t bLb = diag ? aLb : smb + 4 * GCH + (buf * 2 + 1) * GCH;
#pragma unroll
        for (int kk = 0; kk < 2; kk++) {
            const uint32_t kbo = kk * 32;
            uint32_t a[4][4], bh[4][2], bl[4][2];
#pragma unroll
            for (int mt = 0; mt < 4; mt++)
                ldsm4(a[mt], aHb + (uint32_t)(m0w + mt * 16 + a_r) * GSTRIDE + a_kb + kbo);
#pragma unroll
            for (int nt2 = 0; nt2 < 2; nt2++) {
                const uint32_t ro = (uint32_t)(n0w + nt2 * 16 + b_r) * GSTRIDE + b_kb + kbo;
                uint32_t t[4];
                ldsm4(t, bHb + ro);
                bh[nt2 * 2][0] = t[0]; bh[nt2 * 2][1] = t[1];
                bh[nt2 * 2 + 1][0] = t[2]; bh[nt2 * 2 + 1][1] = t[3];
                ldsm4(t, bLb + ro);
                bl[nt2 * 2][0] = t[0]; bl[nt2 * 2][1] = t[1];
                bl[nt2 * 2 + 1][0] = t[2]; bl[nt2 * 2 + 1][1] = t[3];
            }
#pragma unroll
            for (int mt = 0; mt < 4; mt++)
#pragma unroll
                for (int nt = 0; nt < 4; nt++) {
                    mma_bf16(acc[mt][nt], a[mt], bh[nt]);
                    mma_bf16(acc[mt][nt], a[mt], bl[nt]);
                }
#pragma unroll
            for (int mt = 0; mt < 4; mt++)
                ldsm4(a[mt], aLb + (uint32_t)(m0w + mt * 16 + a_r) * GSTRIDE + a_kb + kbo);
#pragma unroll
            for (int mt = 0; mt < 4; mt++)
#pragma unroll
                for (int nt = 0; nt < 4; nt++)
                    mma_bf16(acc[mt][nt], a[mt], bh[nt]);
        }
    }

    float* gout = &g_gramp[ks][n][0][0];
#pragma unroll
    for (int mt = 0; mt < 4; mt++)
#pragma unroll
        for (int h = 0; h < 2; h++) {
            const int c = c0 + m0w + mt * 16 + (lane >> 2) + h * 8;
#pragma unroll
            for (int nt = 0; nt < 4; nt++) {
                const int d = d0 + n0w + nt * 8 + (lane & 3) * 2;
                const float v0 = acc[mt][nt][h * 2], v1 = acc[mt][nt][h * 2 + 1];
                *(float2*)(gout + (size_t)c * CC + d) = make_float2(v0, v1);
                if (!diag) {
                    gout[(size_t)d * CC + c] = v0;
                    gout[(size_t)(d + 1) * CC + c] = v1;
                }
            }
        }
}

// ---- t7^T packed (split bf16, pre-scaled by 1/896) ---------------------------
__global__ void k_t7(const float* __restrict__ Wg1, const float* __restrict__ bg1,
                     const float* __restrict__ Wg2, const float* __restrict__ bg2,
                     const float* __restrict__ p7w) {
    __shared__ float W1s[32][33], W2s[32][33], Gs[32][33], Ms[32][33];
    const int n = blockIdx.z, g = blockIdx.y, h = blockIdx.x;
    const int tx = threadIdx.x, ty = threadIdx.y;

    W1s[ty][tx] = Wg1[(g * 32 + ty) * 32 + tx];
    W2s[ty][tx] = Wg2[(h * 32 + ty) * 32 + tx];
    Gs[ty][tx]  = g_gramp[0][n][g * 32 + ty][h * 32 + tx]
                + g_gramp[1][n][g * 32 + ty][h * 32 + tx]
                + g_gramp[2][n][g * 32 + ty][h * 32 + tx];
    __syncthreads();

    float m = 0.f;
#pragma unroll
    for (int i = 0; i < 32; i++) m += W1s[ty][i] * Gs[i][tx];
    Ms[ty][tx] = m;
    __syncthreads();

    float t5 = 0.f;
#pragma unroll
    for (int j = 0; j < 32; j++) t5 += Ms[ty][j] * W2s[tx][j];

    const int c = g * 32 + ty, d = h * 32 + tx;
    const float b1 = bg1[c], b2 = bg2[d];
    t5 += b1 * g_v[n][d] + g_u[n][c] * b2 + (float)HW * b1 * b2;
    const float val = p7w[c * 256 + d] * t5 * (1.0f / 896.0f);

    __syncthreads();
    W1s[ty][tx] = val;
    __syncthreads();
    const float tv = W1s[tx][ty];          // t7[c=g*32+tx][d=h*32+ty]
    const int dd = h * 32 + ty, cc = g * 32 + tx;
    __nv_bfloat16 hh = __float2bfloat16(tv);
    g_t7k[n][0][cc >> 4][dd * 24 + (cc & 15)] = hh;
    g_t7k[n][1][cc >> 4][dd * 24 + (cc & 15)] =
        __float2bfloat16(tv - __bfloat162float(hh));
}

// ---- fused: warp-decoupled mbarrier pipeline, N=128, 512 thr -----------------
#define BCHK 20480u
#define B_LO 81920u
#define AOFF 163840u
#define FACH 12288u
#define FUSED_SMEM (163840 + 4 * 12288)   // 212992
#define ACHB 24576u

__global__ __launch_bounds__(512, 1) void k_fused(const float* __restrict__ bp3,
                                                  float* __restrict__ out) {
    extern __shared__ char sm[];
    __shared__ alignas(8) uint64_t s_mb[5];   // fullA0, fullA1, emptyA0, emptyA1, fullB
    const int n = blockIdx.y, sx = blockIdx.x;
    const int tid = threadIdx.x, lane = tid & 31, wid = tid >> 5;
    const int m0w = (wid >> 2) * 64, n0w = (wid & 3) * 32;
    const uint32_t smb = smem_u32(sm);
    const uint32_t mbF0 = smem_u32(&s_mb[0]);
    const uint32_t mbF1 = mbF0 + 8, mbE0 = mbF0 + 16, mbE1 = mbF0 + 24;
    const uint32_t mbB = mbF0 + 32;
    const bool tail = (sx == 24);
    const int nchk = tail ? 2 : 4;

    auto issueA = [&](int g1, int buf) {   // single thread (tid 0)
        const char* Ah = (g1 < 16) ? (const char*)&g_wpk[0][g1 & 15][0]
                                   : (const char*)&g_t7k[n][0][g1 & 15][0];
        const char* Al = (g1 < 16) ? (const char*)&g_wpk[1][g1 & 15][0]
                                   : (const char*)&g_t7k[n][1][g1 & 15][0];
        const uint32_t mb = buf ? mbF1 : mbF0;
        MBAR_EXPECT(mb, ACHB);
        bulkcp(smb + AOFF + (buf * 2 + 0) * FACH, Ah, FACH, mb);
        bulkcp(smb + AOFF + (buf * 2 + 1) * FACH, Al, FACH, mb);
    };

    if (tid == 0) {
        MBAR_INIT(mbF0, 1); MBAR_INIT(mbF1, 1);
        MBAR_INIT(mbE0, 16); MBAR_INIT(mbE1, 16);
        MBAR_INIT(mbB, 1);
    }
    __syncthreads();
    if (tid == 0) {
        MBAR_EXPECT(mbB, (uint32_t)nchk * 2u * BCHK);
        for (int p = 0; p < nchk; p++) {
            const char* base = (const char*)&g_xgk[n][4 * sx + p][0][0];
            bulkcp(smb + p * BCHK, base, BCHK, mbB);
            bulkcp(smb + B_LO + p * BCHK, base + BCHK, BCHK, mbB);
        }
        issueA(0, 0);
        issueA(1, 1);
    }

    float acc[4][4][4];
#pragma unroll
    for (int i = 0; i < 4; i++)
#pragma unroll
        for (int j = 0; j < 4; j++)
#pragma unroll
            for (int p = 0; p < 4; p++) acc[i][j][p] = 0.f;

    const int a_r = lane & 15, a_kb = (lane >> 4) * 16;
    const int bt_r = (lane & 7) + 8 * ((lane >> 3) & 1);
    const int bt_nb = (lane >> 4) * 16;
    int phF0 = 0, phF1 = 0;      // per-warp full phases
    int phE0 = 0, phE1 = 0;      // producer (tid 0) empty phases

    for (int g = 0; g < 32; g++) {
        const int buf = g & 1;
        if (buf == 0) { MBAR_WAIT(mbF0, phF0); phF0 ^= 1; }
        else          { MBAR_WAIT(mbF1, phF1); phF1 ^= 1; }
        if (g == 0) MBAR_WAIT(mbB, 0);

        if (g == 16) {
            __syncthreads();   // all stage-1 B reads done
            // stage0 epilogue: t6 = max(t3 + bias, sin(pi/2 x)); rewrite B
#pragma unroll
            for (int mt = 0; mt < 4; mt++)
#pragma unroll
                for (int h = 0; h < 2; h++) {
                    const int c = m0w + mt * 16 + (lane >> 2) + h * 8;
                    const float bias = __ldg(&bp3[c]);
#pragma unroll
                    for (int nt = 0; nt < 4; nt++) {
                        const int j = n0w + nt * 8 + (lane & 3) * 2;
                        const uint32_t off = (uint32_t)(j >> 5) * BCHK
                                           + (uint32_t)c * 80u + (j & 31) * 2;
                        uint32_t* ph = (uint32_t*)(sm + off);
                        uint32_t* pl = (uint32_t*)(sm + B_LO + off);
                        const uint32_t vh = *ph, vl = *pl;
                        const float x0 = bflo(vh) + bflo(vl);
                        const float x1 = bfhi(vh) + bfhi(vl);
                        const float t60 = fmaxf(acc[mt][nt][h * 2] + bias,
                                                __sinf(PI_HALF * x0));
                        const float t61 = fmaxf(acc[mt][nt][h * 2 + 1] + bias,
                                                __sinf(PI_HALF * x1));
                        __nv_bfloat16 h0 = __float2bfloat16(t60);
                        __nv_bfloat16 h1 = __float2bfloat16(t61);
                        *ph = pk2(h0, h1);
                        *pl = pk2(__float2bfloat16(t60 - __bfloat162float(h0)),
                                  __float2bfloat16(t61 - __bfloat162float(h1)));
                        acc[mt][nt][h * 2] = 0.f;
                        acc[mt][nt][h * 2 + 1] = 0.f;
                    }
                }
            __syncthreads();   // t6 visible to all warps
        }

        const uint32_t aHb = smb + AOFF + (buf * 2 + 0) * FACH;
        const uint32_t aLb = smb + AOFF + (buf * 2 + 1) * FACH;
        const int kg = (g & 15) * 16;
        uint32_t a[4][4], bh[4][2], bl[4][2];
#pragma unroll
        for (int mt = 0; mt < 4; mt++)
            ldsm4(a[mt], aHb + (uint32_t)(m0w + mt * 16 + a_r) * 48u + a_kb);
#pragma unroll
        for (int nt2 = 0; nt2 < 2; nt2++) {
            const int jcol = n0w + nt2 * 16;
            const uint32_t ro = (uint32_t)(jcol >> 5) * BCHK
                              + (uint32_t)(kg + bt_r) * 80u
                              + (jcol & 31) * 2 + bt_nb;
            uint32_t t[4];
            ldsm4t(t, smb + ro);
            bh[nt2 * 2][0] = t[0]; bh[nt2 * 2][1] = t[1];
            bh[nt2 * 2 + 1][0] = t[2]; bh[nt2 * 2 + 1][1] = t[3];
            ldsm4t(t, smb + B_LO + ro);
            bl[nt2 * 2][0] = t[0]; bl[nt2 * 2][1] = t[1];
            bl[nt2 * 2 + 1][0] = t[2]; bl[nt2 * 2 + 1][1] = t[3];
        }
#pragma unroll
        for (int mt = 0; mt < 4; mt++)
#pragma unroll
            for (int nt = 0; nt < 4; nt++) {
                mma_bf16(acc[mt][nt], a[mt], bh[nt]);
                mma_bf16(acc[mt][nt], a[mt], bl[nt]);
            }
#pragma unroll
        for (int mt = 0; mt < 4; mt++)
            ldsm4(a[mt], aLb + (uint32_t)(m0w + mt * 16 + a_r) * 48u + a_kb);
#pragma unroll
        for (int mt = 0; mt < 4; mt++)
#pragma unroll
            for (int nt = 0; nt < 4; nt++)
                mma_bf16(acc[mt][nt], a[mt], bh[nt]);

        // consumption done: per-warp arrive; producer refills after all 16 arrive
        if (lane == 0) MBAR_ARRIVE(buf ? mbE1 : mbE0);
        if (tid == 0 && g + 2 < 32) {
            if (buf == 0) { MBAR_WAIT(mbE0, phE0); phE0 ^= 1; }
            else          { MBAR_WAIT(mbE1, phE1); phE1 ^= 1; }
            issueA(g + 2, buf);
        }
    }

    float* ob = out + (size_t)n * CC * HW + (size_t)sx * 128;
#pragma unroll
    for (int mt = 0; mt < 4; mt++)
#pragma unroll
        for (int h = 0; h < 2; h++) {
            const int d = m0w + mt * 16 + (lane >> 2) + h * 8;
#pragma unroll
            for (int nt = 0; nt < 4; nt++) {
                const int j = n0w + nt * 8 + (lane & 3) * 2;
                if (!tail || j < 64)
                    *(float2*)(ob + (size_t)d * HW + j) =
                        make_float2(acc[mt][nt][h * 2], acc[mt][nt][h * 2 + 1]);
            }
        }
}

extern "C" void kernel_launch(void* const* d_in, const int* in_sizes, int n_in,
                              void* d_out, int out_size) {
    (void)in_sizes; (void)n_in; (void)out_size;
    const float* x   = (const float*)d_in[0];
    const float* Wp3 = (const float*)d_in[1];
    const float* bp3 = (const float*)d_in[2];
    const float* Wg1 = (const float*)d_in[3];
    const float* bg1 = (const float*)d_in[4];
    const float* Wg2 = (const float*)d_in[5];
    const float* bg2 = (const float*)d_in[6];
    const float* p7w = (const float*)d_in[7];
    float* out = (float*)d_out;

    cudaFuncSetAttribute(k_gram,  cudaFuncAttributeMaxDynamicSharedMemorySize, GRAM_SMEM);
    cudaFuncSetAttribute(k_fused, cudaFuncAttributeMaxDynamicSharedMemorySize, FUSED_SMEM);

    k_wprep<<<256, 256>>>(Wp3);
    k_prep<<<dim3(256, 32), 256>>>(x);
    k_gram<<<dim3(3, 32, 3), 256, GRAM_SMEM>>>();
    k_uv<<<32, 256>>>(Wg1, Wg2);
    k_t7<<<dim3(8, 8, 32), dim3(32, 32)>>>(Wg1, bg1, Wg2, bg2, p7w);
    k_fused<<<dim3(25, 32), 512, FUSED_SMEM>>>(bp3, out);
}